// round 11
// baseline (speedup 1.0000x reference)
#include <cuda_runtime.h>
#include <cuda_bf16.h>
#include <math.h>

#define BATCH 256
#define TWOB 512
#define DIM 2048
#define HW 64
#define INV_TEMP 10.0f
#define BN_EPS 1e-5f
#define COS_EPS 1e-8f
#define SLICE_RANGE 2

typedef __nv_bfloat16 bf16;

// ---- scratch (device globals: no allocations allowed) ----
__device__ bf16  g_pb[TWOB * DIM];         // pooled, bf16
__device__ bf16  g_W1b[DIM * DIM];
__device__ bf16  g_W2b[DIM * DIM];
__device__ float g_hp[2 * TWOB * DIM];     // GEMM1 split-K partials
__device__ float g_ps[DIM * 32];           // bn partial sums  [col][chunk]
__device__ float g_pq[DIM * 32];           // bn partial sumsq [col][chunk]
__device__ float g_ga[DIM];                // gamma * istd
__device__ float g_be[DIM];                // beta - mu * ga
__device__ bf16  g_hb[TWOB * DIM];         // BN+ReLU, bf16
__device__ float g_zp[2 * TWOB * DIM];     // GEMM2 split-K partials
__device__ bf16  g_znb[TWOB * DIM];        // normalized rows, bf16
__device__ float g_simp[4 * BATCH * TWOB]; // sim split-K partials
__device__ float g_lossb[BATCH];
__device__ float g_cntd[BATCH];
__device__ unsigned g_c1 = 0;              // bn_stats completion counter
__device__ unsigned g_c2 = 0;              // loss completion counter

__device__ __forceinline__ unsigned smem_u32(const void* p) {
    return (unsigned)__cvta_generic_to_shared(p);
}

// ---------------------------------------------------------------------------
// 1) prep: spatial mean pool (block range A) + weight f32->bf16 (block range B)
// ---------------------------------------------------------------------------
#define POOL_BLOCKS ((TWOB * DIM / 2) / 8)          // 65536
#define CVT_BLOCKS  ((2 * DIM * DIM / 4) / 256)     // 8192

__global__ void prep_kernel(const float* __restrict__ z0,
                            const float* __restrict__ z1,
                            const float* __restrict__ W1,
                            const float* __restrict__ W2) {
    if (blockIdx.x < POOL_BLOCKS) {
        int gt   = blockIdx.x * 256 + threadIdx.x;
        int warp = gt >> 5;
        int lane = gt & 31;
        int ch   = warp * 2 + (lane >> 4);
        const float* src = (ch < BATCH * DIM)
                             ? z0 + (size_t)ch * HW
                             : z1 + (size_t)(ch - BATCH * DIM) * HW;
        float4 v = ((const float4*)src)[lane & 15];
        float s = (v.x + v.y) + (v.z + v.w);
#pragma unroll
        for (int o = 8; o > 0; o >>= 1)
            s += __shfl_xor_sync(0xffffffffu, s, o);
        if ((lane & 15) == 0) g_pb[ch] = __float2bfloat16(s * (1.0f / 64.0f));
    } else {
        const int NPER = DIM * DIM / 4;
        int i = (blockIdx.x - POOL_BLOCKS) * 256 + threadIdx.x;
        const float* src;
        bf16* dst;
        int j;
        if (i < NPER) { src = W1; dst = g_W1b; j = i; }
        else          { src = W2; dst = g_W2b; j = i - NPER; }
        float4 v = ((const float4*)src)[j];
        ((__nv_bfloat162*)dst)[j * 2]     = __floats2bfloat162_rn(v.x, v.y);
        ((__nv_bfloat162*)dst)[j * 2 + 1] = __floats2bfloat162_rn(v.z, v.w);
    }
}

// ---------------------------------------------------------------------------
// 2) bf16 GEMM: C[M,N] = A[M,K]*B[N,K]^T (+bias). 64x64 tile, 4 warps (2x2),
//    warp tile 32x32. 3-stage cp.async pipeline (ONE barrier per K-iter),
//    ldmatrix.x4 fragments. blockIdx.z = split-K chunk.
// ---------------------------------------------------------------------------
#define BK 32
#define SPAD 40   // bf16 per smem row (80B): conflict-free ldmatrix

__global__ void __launch_bounds__(128, 4) gemm_kernel(
    const bf16* __restrict__ A, const bf16* __restrict__ Bm,
    float* __restrict__ C, const float* __restrict__ bias,
    int N, int K, int kChunk, int Mtot) {
    constexpr int BM = 64, BN = 64, TPB = 128;
    __shared__ bf16 As[3][BM * SPAD];
    __shared__ bf16 Bs[3][BN * SPAD];

    const int tid  = threadIdx.x;
    const int warp = tid >> 5;
    const int lane = tid & 31;
    const int wm = warp >> 1;
    const int wn = warp & 1;
    const int rowBase = blockIdx.y * BM;
    const int colBase = blockIdx.x * BN;
    const int kOff    = blockIdx.z * kChunk;
    float* Cout = C + (size_t)blockIdx.z * Mtot * N;

    const bf16* Ag = A + (size_t)rowBase * K + kOff;
    const bf16* Bg = Bm + (size_t)colBase * K + kOff;

    auto loadStage = [&](int st, int it) {
        int kb = it * BK;
#pragma unroll
        for (int c = tid; c < BM * 4; c += TPB) {
            int r = c >> 2, chk = c & 3;
            unsigned sa = smem_u32(&As[st][r * SPAD + chk * 8]);
            asm volatile("cp.async.cg.shared.global [%0], [%1], 16;\n"
                         :: "r"(sa), "l"(Ag + (size_t)r * K + kb + chk * 8));
        }
#pragma unroll
        for (int c = tid; c < BN * 4; c += TPB) {
            int r = c >> 2, chk = c & 3;
            unsigned sa = smem_u32(&Bs[st][r * SPAD + chk * 8]);
            asm volatile("cp.async.cg.shared.global [%0], [%1], 16;\n"
                         :: "r"(sa), "l"(Bg + (size_t)r * K + kb + chk * 8));
        }
        asm volatile("cp.async.commit_group;\n");
    };

    float acc[2][4][4];
#pragma unroll
    for (int i = 0; i < 2; i++)
#pragma unroll
        for (int j = 0; j < 4; j++)
#pragma unroll
            for (int k = 0; k < 4; k++) acc[i][j][k] = 0.f;

    const int NIT = kChunk / BK;
    loadStage(0, 0);
    loadStage(1, 1);

    const int arow = lane & 15;
    const int acol = (lane >> 4) * 8;

    for (int it = 0; it < NIT; ++it) {
        asm volatile("cp.async.wait_group 1;\n" ::: "memory");
        // Single barrier per iteration: also orders buffer reuse — after this
        // barrier all warps have finished compute on iteration it-1, which was
        // the last reader of buffer (it+2)%3 that the next loadStage overwrites.
        __syncthreads();
        if (it + 2 < NIT) loadStage((it + 2) % 3, it + 2);
        else asm volatile("cp.async.commit_group;\n");
        const int buf = it % 3;

#pragma unroll
        for (int ks = 0; ks < 2; ++ks) {
            unsigned afr[2][4], bfr[2][4];
#pragma unroll
            for (int mt = 0; mt < 2; mt++) {
                unsigned sa = smem_u32(
                    &As[buf][(wm * 32 + mt * 16 + arow) * SPAD + acol + ks * 16]);
                asm volatile(
                    "ldmatrix.sync.aligned.m8n8.x4.shared.b16 {%0,%1,%2,%3}, [%4];\n"
                    : "=r"(afr[mt][0]), "=r"(afr[mt][1]),
                      "=r"(afr[mt][2]), "=r"(afr[mt][3]) : "r"(sa));
            }
#pragma unroll
            for (int np = 0; np < 2; np++) {
                unsigned sa = smem_u32(
                    &Bs[buf][(wn * 32 + np * 16 + arow) * SPAD + acol + ks * 16]);
                asm volatile(
                    "ldmatrix.sync.aligned.m8n8.x4.shared.b16 {%0,%1,%2,%3}, [%4];\n"
                    : "=r"(bfr[np][0]), "=r"(bfr[np][1]),
                      "=r"(bfr[np][2]), "=r"(bfr[np][3]) : "r"(sa));
            }
#pragma unroll
            for (int mt = 0; mt < 2; mt++)
#pragma unroll
                for (int nt = 0; nt < 4; nt++) {
                    asm volatile(
                        "mma.sync.aligned.m16n8k16.row.col.f32.bf16.bf16.f32 "
                        "{%0,%1,%2,%3}, {%4,%5,%6,%7}, {%8,%9}, {%0,%1,%2,%3};\n"
                        : "+f"(acc[mt][nt][0]), "+f"(acc[mt][nt][1]),
                          "+f"(acc[mt][nt][2]), "+f"(acc[mt][nt][3])
                        : "r"(afr[mt][0]), "r"(afr[mt][1]),
                          "r"(afr[mt][2]), "r"(afr[mt][3]),
                          "r"(bfr[nt >> 1][nt & 1]), "r"(bfr[nt >> 1][2 + (nt & 1)]));
                }
        }
    }

    const int g  = lane >> 2;
    const int t4 = lane & 3;
    const bool addb = (bias != nullptr) && (blockIdx.z == 0);
#pragma unroll
    for (int mt = 0; mt < 2; mt++) {
        int r0 = rowBase + wm * 32 + mt * 16 + g;
#pragma unroll
        for (int nt = 0; nt < 4; nt++) {
            int c0 = colBase + wn * 32 + nt * 8 + t4 * 2;
            float bx = addb ? bias[c0] : 0.f;
            float by = addb ? bias[c0 + 1] : 0.f;
            *(float2*)&Cout[(size_t)r0 * N + c0] =
                make_float2(acc[mt][nt][0] + bx, acc[mt][nt][1] + by);
            *(float2*)&Cout[(size_t)(r0 + 8) * N + c0] =
                make_float2(acc[mt][nt][2] + bx, acc[mt][nt][3] + by);
        }
    }
}

// ---------------------------------------------------------------------------
// 3) BN stats (grid (8,32)) with fused finalize in the last-arriving block.
//    Partials stored transposed: g_ps[col*32 + chunk].
// ---------------------------------------------------------------------------
__global__ void bn_stats_kernel(const float* __restrict__ gamma,
                                const float* __restrict__ beta) {
    int col = blockIdx.x * 256 + threadIdx.x;
    int r0  = blockIdx.y * 16;
    float s = 0.f, q = 0.f;
#pragma unroll
    for (int r = 0; r < 16; r++) {
        size_t i = (size_t)(r0 + r) * DIM + col;
        float v = g_hp[i] + g_hp[TWOB * (size_t)DIM + i];
        s += v; q += v * v;
    }
    g_ps[col * 32 + blockIdx.y] = s;
    g_pq[col * 32 + blockIdx.y] = q;

    __threadfence();
    __shared__ unsigned ticket;
    if (threadIdx.x == 0) ticket = atomicAdd(&g_c1, 1u);
    __syncthreads();
    if (ticket == 255) {                 // last block finalizes all columns
        if (threadIdx.x == 0) g_c1 = 0;  // reset for next graph replay
        __threadfence();
        // warp per column batch: each warp handles columns, lane per chunk
        int lane = threadIdx.x & 31;
        int wid  = threadIdx.x >> 5;     // 0..7
        for (int c = wid; c < DIM; c += 8) {
            float ss = g_ps[c * 32 + lane];
            float qq = g_pq[c * 32 + lane];
#pragma unroll
            for (int o = 16; o > 0; o >>= 1) {
                ss += __shfl_xor_sync(0xffffffffu, ss, o);
                qq += __shfl_xor_sync(0xffffffffu, qq, o);
            }
            if (lane == 0) {
                float mu   = ss * (1.f / TWOB);
                float var  = qq * (1.f / TWOB) - mu * mu;
                float istd = rsqrtf(var + BN_EPS);
                float ga = gamma[c] * istd;
                g_ga[c] = ga;
                g_be[c] = beta[c] - mu * ga;
            }
        }
    }
}

// ---------------------------------------------------------------------------
// 4) BN apply + ReLU -> bf16: fully coalesced float4 walk (1024 blocks)
// ---------------------------------------------------------------------------
__global__ void bn_apply_kernel() {
    int i4 = blockIdx.x * 256 + threadIdx.x;      // float4 index
    int c4 = i4 & (DIM / 4 - 1);                  // float4 index within row
    float4 a = ((const float4*)g_hp)[i4];
    float4 b = ((const float4*)(g_hp + TWOB * (size_t)DIM))[i4];
    float4 ga = ((const float4*)g_ga)[c4];
    float4 be = ((const float4*)g_be)[c4];
    float v0 = fmaxf((a.x + b.x) * ga.x + be.x, 0.f);
    float v1 = fmaxf((a.y + b.y) * ga.y + be.y, 0.f);
    float v2 = fmaxf((a.z + b.z) * ga.z + be.z, 0.f);
    float v3 = fmaxf((a.w + b.w) * ga.w + be.w, 0.f);
    __nv_bfloat162* dst = (__nv_bfloat162*)g_hb;
    dst[i4 * 2]     = __floats2bfloat162_rn(v0, v1);
    dst[i4 * 2 + 1] = __floats2bfloat162_rn(v2, v3);
}

// ---------------------------------------------------------------------------
// 5) row L2 normalize (combines 2 z partials) -> bf16
// ---------------------------------------------------------------------------
__global__ void rownorm_kernel() {
    __shared__ float red[256];
    int r = blockIdx.x, tid = threadIdx.x;
    const float4* p0 = (const float4*)(g_zp + (size_t)r * DIM);
    const float4* p1 = (const float4*)(g_zp + TWOB * (size_t)DIM + (size_t)r * DIM);
    float4 a0 = p0[tid], a1 = p1[tid];
    float4 b0 = p0[tid + 256], b1 = p1[tid + 256];
    float4 a = make_float4(a0.x + a1.x, a0.y + a1.y, a0.z + a1.z, a0.w + a1.w);
    float4 b = make_float4(b0.x + b1.x, b0.y + b1.y, b0.z + b1.z, b0.w + b1.w);
    float s = a.x * a.x + a.y * a.y + a.z * a.z + a.w * a.w
            + b.x * b.x + b.y * b.y + b.z * b.z + b.w * b.w;
    red[tid] = s;
    __syncthreads();
    for (int o = 128; o > 0; o >>= 1) {
        if (tid < o) red[tid] += red[tid + o];
        __syncthreads();
    }
    float inv = 1.f / fmaxf(sqrtf(red[0]), COS_EPS);
    __nv_bfloat162* dst = (__nv_bfloat162*)(g_znb + (size_t)r * DIM);
    dst[tid * 2]             = __floats2bfloat162_rn(a.x * inv, a.y * inv);
    dst[tid * 2 + 1]         = __floats2bfloat162_rn(a.z * inv, a.w * inv);
    dst[(tid + 256) * 2]     = __floats2bfloat162_rn(b.x * inv, b.y * inv);
    dst[(tid + 256) * 2 + 1] = __floats2bfloat162_rn(b.z * inv, b.w * inv);
}

// ---------------------------------------------------------------------------
// 6) per-row contrastive loss (sums 4 K-partials) + fused final reduce
// ---------------------------------------------------------------------------
__global__ void loss_rows_kernel(const int* __restrict__ rel,
                                 float* __restrict__ out, int out_size) {
    __shared__ float red[256];
    __shared__ float rc[256];
    int i = blockIdx.x, j = threadIdx.x;
    int ri = rel[i];
    int rj = rel[j];
    float s1 = 0.f, s2 = 0.f;
#pragma unroll
    for (int p = 0; p < 4; p++) {
        s1 += g_simp[p * BATCH * TWOB + i * TWOB + j];
        s2 += g_simp[p * BATCH * TWOB + i * TWOB + BATCH + j];
    }
    float e1 = expf(s1 * INV_TEMP);
    float e2 = expf(s2 * INV_TEMP);
    int diff = ri - rj; if (diff < 0) diff = -diff;
    bool isneg = diff > SLICE_RANGE;
    bool ispos = (diff <= SLICE_RANGE) && (j != i);

    red[j] = (isneg ? e1 : 0.f) + e2;
    __syncthreads();
    for (int o = 128; o > 0; o >>= 1) {
        if (j < o) red[j] += red[j + o];
        __syncthreads();
    }
    float neg_sum = red[0];
    __syncthreads();

    red[j] = ispos ? (logf(e1 + neg_sum) - s1 * INV_TEMP) : 0.f;
    rc[j]  = ispos ? 1.f : 0.f;
    __syncthreads();
    for (int o = 128; o > 0; o >>= 1) {
        if (j < o) { red[j] += red[j + o]; rc[j] += rc[j + o]; }
        __syncthreads();
    }
    if (j == 0) {
        float cnt = rc[0];
        g_lossb[i] = (cnt > 0.f) ? (red[0] / cnt) : 0.f;
        g_cntd[i]  = (cnt > 0.f) ? 1.f : 0.f;
    }

    __threadfence();
    __shared__ unsigned ticket;
    if (j == 0) ticket = atomicAdd(&g_c2, 1u);
    __syncthreads();
    if (ticket == BATCH - 1) {
        if (j == 0) g_c2 = 0;   // reset for next graph replay
        __threadfence();
        red[j] = g_lossb[j];
        rc[j]  = g_cntd[j];
        __syncthreads();
        for (int o = 128; o > 0; o >>= 1) {
            if (j < o) { red[j] += red[j + o]; rc[j] += rc[j + o]; }
            __syncthreads();
        }
        if (j == 0) {
            out[0] = red[0];
            if (out_size > 1) out[1] = rc[0];
        }
    }
}

// ---------------------------------------------------------------------------
extern "C" void kernel_launch(void* const* d_in, const int* in_sizes, int n_in,
                              void* d_out, int out_size) {
    const float* z0    = (const float*)d_in[0];
    const float* z1    = (const float*)d_in[1];
    const int*   rel0  = (const int*)d_in[2];
    const float* W1    = (const float*)d_in[4];
    const float* b1    = (const float*)d_in[5];
    const float* gamma = (const float*)d_in[6];
    const float* beta  = (const float*)d_in[7];
    const float* W2    = (const float*)d_in[8];
    const float* b2    = (const float*)d_in[9];

    void *pb_, *w1b_, *w2b_, *hp_, *hb_, *zp_, *znb_, *simp_;
    cudaGetSymbolAddress(&pb_,  g_pb);
    cudaGetSymbolAddress(&w1b_, g_W1b);
    cudaGetSymbolAddress(&w2b_, g_W2b);
    cudaGetSymbolAddress(&hp_,  g_hp);
    cudaGetSymbolAddress(&hb_,  g_hb);
    cudaGetSymbolAddress(&zp_,  g_zp);
    cudaGetSymbolAddress(&znb_, g_znb);
    cudaGetSymbolAddress(&simp_, g_simp);

    // 1) pool + weight conversion
    prep_kernel<<<POOL_BLOCKS + CVT_BLOCKS, 256>>>(z0, z1, W1, W2);
    // 2) GEMM1: h = p @ W1^T + b1, split-K=2 -> 512 CTAs
    gemm_kernel<<<dim3(DIM / 64, TWOB / 64, 2), 128>>>(
        (const bf16*)pb_, (const bf16*)w1b_, (float*)hp_, b1,
        DIM, DIM, DIM / 2, TWOB);
    // 3) BN stats + fused finalize (last-ticket block)
    bn_stats_kernel<<<dim3(8, 32), 256>>>(gamma, beta);
    // 4) coalesced BN apply + ReLU -> bf16
    bn_apply_kernel<<<(TWOB * DIM / 4) / 256, 256>>>();
    // 5) GEMM2: z = hb @ W2^T + b2, split-K=2 -> 512 CTAs
    gemm_kernel<<<dim3(DIM / 64, TWOB / 64, 2), 128>>>(
        (const bf16*)hb_, (const bf16*)w2b_, (float*)zp_, b2,
        DIM, DIM, DIM / 2, TWOB);
    // 6) row normalize (combine partials) -> bf16
    rownorm_kernel<<<TWOB, 256>>>();
    // 7) sim partials: 64x64 tiles, split-K=4 -> 128 CTAs
    gemm_kernel<<<dim3(TWOB / 64, BATCH / 64, 4), 128>>>(
        (const bf16*)znb_, (const bf16*)znb_, (float*)simp_, nullptr,
        TWOB, DIM, DIM / 4, BATCH);
    // 8) per-row loss + fused deterministic finalize
    loss_rows_kernel<<<BATCH, 256>>>(rel0, (float*)d_out, out_size);
}

// round 12
// speedup vs baseline: 1.0054x; 1.0054x over previous
#include <cuda_runtime.h>
#include <cuda_bf16.h>
#include <math.h>

#define BATCH 256
#define TWOB 512
#define DIM 2048
#define HW 64
#define INV_TEMP 10.0f
#define BN_EPS 1e-5f
#define COS_EPS 1e-8f
#define SLICE_RANGE 2

typedef __nv_bfloat16 bf16;

// ---- scratch (device globals: no allocations allowed) ----
__device__ bf16  g_pb[TWOB * DIM];         // pooled, bf16
__device__ bf16  g_W1b[DIM * DIM];
__device__ bf16  g_W2b[DIM * DIM];
__device__ float g_hp[2 * TWOB * DIM];     // GEMM1 split-K partials
__device__ float g_ps[DIM * 32];           // bn partial sums  [col][chunk]
__device__ float g_pq[DIM * 32];           // bn partial sumsq [col][chunk]
__device__ float g_ga[DIM];                // gamma * istd
__device__ float g_be[DIM];                // beta - mu * ga
__device__ bf16  g_hb[TWOB * DIM];         // BN+ReLU, bf16
__device__ float g_zp[2 * TWOB * DIM];     // GEMM2 split-K partials
__device__ bf16  g_znb[TWOB * DIM];        // normalized rows, bf16
__device__ float g_simp[4 * BATCH * TWOB]; // sim split-K partials
__device__ float g_lossb[BATCH];
__device__ float g_cntd[BATCH];
__device__ unsigned g_c1 = 0;              // bn_stats completion counter
__device__ unsigned g_c2 = 0;              // loss completion counter

__device__ __forceinline__ unsigned smem_u32(const void* p) {
    return (unsigned)__cvta_generic_to_shared(p);
}

// ---------------------------------------------------------------------------
// 1) prep: spatial mean pool (block range A) + weight f32->bf16 (block range B)
// ---------------------------------------------------------------------------
#define POOL_BLOCKS ((TWOB * DIM / 2) / 8)          // 65536
#define CVT_BLOCKS  ((2 * DIM * DIM / 4) / 256)     // 8192

__global__ void prep_kernel(const float* __restrict__ z0,
                            const float* __restrict__ z1,
                            const float* __restrict__ W1,
                            const float* __restrict__ W2) {
    if (blockIdx.x < POOL_BLOCKS) {
        int gt   = blockIdx.x * 256 + threadIdx.x;
        int warp = gt >> 5;
        int lane = gt & 31;
        int ch   = warp * 2 + (lane >> 4);
        const float* src = (ch < BATCH * DIM)
                             ? z0 + (size_t)ch * HW
                             : z1 + (size_t)(ch - BATCH * DIM) * HW;
        float4 v = ((const float4*)src)[lane & 15];
        float s = (v.x + v.y) + (v.z + v.w);
#pragma unroll
        for (int o = 8; o > 0; o >>= 1)
            s += __shfl_xor_sync(0xffffffffu, s, o);
        if ((lane & 15) == 0) g_pb[ch] = __float2bfloat16(s * (1.0f / 64.0f));
    } else {
        const int NPER = DIM * DIM / 4;
        int i = (blockIdx.x - POOL_BLOCKS) * 256 + threadIdx.x;
        const float* src;
        bf16* dst;
        int j;
        if (i < NPER) { src = W1; dst = g_W1b; j = i; }
        else          { src = W2; dst = g_W2b; j = i - NPER; }
        float4 v = ((const float4*)src)[j];
        ((__nv_bfloat162*)dst)[j * 2]     = __floats2bfloat162_rn(v.x, v.y);
        ((__nv_bfloat162*)dst)[j * 2 + 1] = __floats2bfloat162_rn(v.z, v.w);
    }
}

// ---------------------------------------------------------------------------
// 2) bf16 GEMM: C[M,N] = A[M,K]*B[N,K]^T (+bias). 64x64 tile, 4 warps (2x2),
//    warp tile 32x32. 3-stage cp.async pipeline, ldmatrix.x4 fragments.
//    blockIdx.z = split-K chunk, writes into partial buffer z*Mtot*N.
//    (exact R10 body — both barriers)
// ---------------------------------------------------------------------------
#define BK 32
#define SPAD 40   // bf16 per smem row (80B): conflict-free ldmatrix

__global__ void __launch_bounds__(128, 4) gemm_kernel(
    const bf16* __restrict__ A, const bf16* __restrict__ Bm,
    float* __restrict__ C, const float* __restrict__ bias,
    int N, int K, int kChunk, int Mtot) {
    constexpr int BM = 64, BN = 64, TPB = 128;
    __shared__ bf16 As[3][BM * SPAD];
    __shared__ bf16 Bs[3][BN * SPAD];

    const int tid  = threadIdx.x;
    const int warp = tid >> 5;
    const int lane = tid & 31;
    const int wm = warp >> 1;
    const int wn = warp & 1;
    const int rowBase = blockIdx.y * BM;
    const int colBase = blockIdx.x * BN;
    const int kOff    = blockIdx.z * kChunk;
    float* Cout = C + (size_t)blockIdx.z * Mtot * N;

    const bf16* Ag = A + (size_t)rowBase * K + kOff;
    const bf16* Bg = Bm + (size_t)colBase * K + kOff;

    auto loadStage = [&](int st, int it) {
        int kb = it * BK;
#pragma unroll
        for (int c = tid; c < BM * 4; c += TPB) {
            int r = c >> 2, chk = c & 3;
            unsigned sa = smem_u32(&As[st][r * SPAD + chk * 8]);
            asm volatile("cp.async.cg.shared.global [%0], [%1], 16;\n"
                         :: "r"(sa), "l"(Ag + (size_t)r * K + kb + chk * 8));
        }
#pragma unroll
        for (int c = tid; c < BN * 4; c += TPB) {
            int r = c >> 2, chk = c & 3;
            unsigned sa = smem_u32(&Bs[st][r * SPAD + chk * 8]);
            asm volatile("cp.async.cg.shared.global [%0], [%1], 16;\n"
                         :: "r"(sa), "l"(Bg + (size_t)r * K + kb + chk * 8));
        }
        asm volatile("cp.async.commit_group;\n");
    };

    float acc[2][4][4];
#pragma unroll
    for (int i = 0; i < 2; i++)
#pragma unroll
        for (int j = 0; j < 4; j++)
#pragma unroll
            for (int k = 0; k < 4; k++) acc[i][j][k] = 0.f;

    const int NIT = kChunk / BK;
    loadStage(0, 0);
    loadStage(1, 1);

    const int arow = lane & 15;
    const int acol = (lane >> 4) * 8;

    for (int it = 0; it < NIT; ++it) {
        asm volatile("cp.async.wait_group 1;\n" ::: "memory");
        __syncthreads();
        if (it + 2 < NIT) loadStage((it + 2) % 3, it + 2);
        else asm volatile("cp.async.commit_group;\n");
        const int buf = it % 3;

#pragma unroll
        for (int ks = 0; ks < 2; ++ks) {
            unsigned afr[2][4], bfr[2][4];
#pragma unroll
            for (int mt = 0; mt < 2; mt++) {
                unsigned sa = smem_u32(
                    &As[buf][(wm * 32 + mt * 16 + arow) * SPAD + acol + ks * 16]);
                asm volatile(
                    "ldmatrix.sync.aligned.m8n8.x4.shared.b16 {%0,%1,%2,%3}, [%4];\n"
                    : "=r"(afr[mt][0]), "=r"(afr[mt][1]),
                      "=r"(afr[mt][2]), "=r"(afr[mt][3]) : "r"(sa));
            }
#pragma unroll
            for (int np = 0; np < 2; np++) {
                unsigned sa = smem_u32(
                    &Bs[buf][(wn * 32 + np * 16 + arow) * SPAD + acol + ks * 16]);
                asm volatile(
                    "ldmatrix.sync.aligned.m8n8.x4.shared.b16 {%0,%1,%2,%3}, [%4];\n"
                    : "=r"(bfr[np][0]), "=r"(bfr[np][1]),
                      "=r"(bfr[np][2]), "=r"(bfr[np][3]) : "r"(sa));
            }
#pragma unroll
            for (int mt = 0; mt < 2; mt++)
#pragma unroll
                for (int nt = 0; nt < 4; nt++) {
                    asm volatile(
                        "mma.sync.aligned.m16n8k16.row.col.f32.bf16.bf16.f32 "
                        "{%0,%1,%2,%3}, {%4,%5,%6,%7}, {%8,%9}, {%0,%1,%2,%3};\n"
                        : "+f"(acc[mt][nt][0]), "+f"(acc[mt][nt][1]),
                          "+f"(acc[mt][nt][2]), "+f"(acc[mt][nt][3])
                        : "r"(afr[mt][0]), "r"(afr[mt][1]),
                          "r"(afr[mt][2]), "r"(afr[mt][3]),
                          "r"(bfr[nt >> 1][nt & 1]), "r"(bfr[nt >> 1][2 + (nt & 1)]));
                }
        }
        __syncthreads();
    }

    const int g  = lane >> 2;
    const int t4 = lane & 3;
    const bool addb = (bias != nullptr) && (blockIdx.z == 0);
#pragma unroll
    for (int mt = 0; mt < 2; mt++) {
        int r0 = rowBase + wm * 32 + mt * 16 + g;
#pragma unroll
        for (int nt = 0; nt < 4; nt++) {
            int c0 = colBase + wn * 32 + nt * 8 + t4 * 2;
            float bx = addb ? bias[c0] : 0.f;
            float by = addb ? bias[c0 + 1] : 0.f;
            *(float2*)&Cout[(size_t)r0 * N + c0] =
                make_float2(acc[mt][nt][0] + bx, acc[mt][nt][1] + by);
            *(float2*)&Cout[(size_t)(r0 + 8) * N + c0] =
                make_float2(acc[mt][nt][2] + bx, acc[mt][nt][3] + by);
        }
    }
}

// ---------------------------------------------------------------------------
// 3) BN stats (grid (8,32)) with fused finalize in the last-arriving block.
//    Partials stored transposed: g_ps[col*32 + chunk].
// ---------------------------------------------------------------------------
__global__ void bn_stats_kernel(const float* __restrict__ gamma,
                                const float* __restrict__ beta) {
    int col = blockIdx.x * 256 + threadIdx.x;
    int r0  = blockIdx.y * 16;
    float s = 0.f, q = 0.f;
#pragma unroll
    for (int r = 0; r < 16; r++) {
        size_t i = (size_t)(r0 + r) * DIM + col;
        float v = g_hp[i] + g_hp[TWOB * (size_t)DIM + i];
        s += v; q += v * v;
    }
    g_ps[col * 32 + blockIdx.y] = s;
    g_pq[col * 32 + blockIdx.y] = q;

    __threadfence();
    __shared__ unsigned ticket;
    if (threadIdx.x == 0) ticket = atomicAdd(&g_c1, 1u);
    __syncthreads();
    if (ticket == 255) {                 // last block finalizes all columns
        if (threadIdx.x == 0) g_c1 = 0;  // reset for next graph replay
        __threadfence();
        int lane = threadIdx.x & 31;
        int wid  = threadIdx.x >> 5;     // 0..7
        for (int c = wid; c < DIM; c += 8) {
            float ss = g_ps[c * 32 + lane];
            float qq = g_pq[c * 32 + lane];
#pragma unroll
            for (int o = 16; o > 0; o >>= 1) {
                ss += __shfl_xor_sync(0xffffffffu, ss, o);
                qq += __shfl_xor_sync(0xffffffffu, qq, o);
            }
            if (lane == 0) {
                float mu   = ss * (1.f / TWOB);
                float var  = qq * (1.f / TWOB) - mu * mu;
                float istd = rsqrtf(var + BN_EPS);
                float ga = gamma[c] * istd;
                g_ga[c] = ga;
                g_be[c] = beta[c] - mu * ga;
            }
        }
    }
}

// ---------------------------------------------------------------------------
// 4) BN apply + ReLU -> bf16: fully coalesced float4 walk (1024 blocks)
// ---------------------------------------------------------------------------
__global__ void bn_apply_kernel() {
    int i4 = blockIdx.x * 256 + threadIdx.x;      // float4 index
    int c4 = i4 & (DIM / 4 - 1);                  // float4 index within row
    float4 a = ((const float4*)g_hp)[i4];
    float4 b = ((const float4*)(g_hp + TWOB * (size_t)DIM))[i4];
    float4 ga = ((const float4*)g_ga)[c4];
    float4 be = ((const float4*)g_be)[c4];
    float v0 = fmaxf((a.x + b.x) * ga.x + be.x, 0.f);
    float v1 = fmaxf((a.y + b.y) * ga.y + be.y, 0.f);
    float v2 = fmaxf((a.z + b.z) * ga.z + be.z, 0.f);
    float v3 = fmaxf((a.w + b.w) * ga.w + be.w, 0.f);
    __nv_bfloat162* dst = (__nv_bfloat162*)g_hb;
    dst[i4 * 2]     = __floats2bfloat162_rn(v0, v1);
    dst[i4 * 2 + 1] = __floats2bfloat162_rn(v2, v3);
}

// ---------------------------------------------------------------------------
// 5) row L2 normalize (combines 2 z partials) -> bf16
// ---------------------------------------------------------------------------
__global__ void rownorm_kernel() {
    __shared__ float red[256];
    int r = blockIdx.x, tid = threadIdx.x;
    const float4* p0 = (const float4*)(g_zp + (size_t)r * DIM);
    const float4* p1 = (const float4*)(g_zp + TWOB * (size_t)DIM + (size_t)r * DIM);
    float4 a0 = p0[tid], a1 = p1[tid];
    float4 b0 = p0[tid + 256], b1 = p1[tid + 256];
    float4 a = make_float4(a0.x + a1.x, a0.y + a1.y, a0.z + a1.z, a0.w + a1.w);
    float4 b = make_float4(b0.x + b1.x, b0.y + b1.y, b0.z + b1.z, b0.w + b1.w);
    float s = a.x * a.x + a.y * a.y + a.z * a.z + a.w * a.w
            + b.x * b.x + b.y * b.y + b.z * b.z + b.w * b.w;
    red[tid] = s;
    __syncthreads();
    for (int o = 128; o > 0; o >>= 1) {
        if (tid < o) red[tid] += red[tid + o];
        __syncthreads();
    }
    float inv = 1.f / fmaxf(sqrtf(red[0]), COS_EPS);
    __nv_bfloat162* dst = (__nv_bfloat162*)(g_znb + (size_t)r * DIM);
    dst[tid * 2]             = __floats2bfloat162_rn(a.x * inv, a.y * inv);
    dst[tid * 2 + 1]         = __floats2bfloat162_rn(a.z * inv, a.w * inv);
    dst[(tid + 256) * 2]     = __floats2bfloat162_rn(b.x * inv, b.y * inv);
    dst[(tid + 256) * 2 + 1] = __floats2bfloat162_rn(b.z * inv, b.w * inv);
}

// ---------------------------------------------------------------------------
// 6) per-row contrastive loss (sums 4 K-partials) + fused final reduce
// ---------------------------------------------------------------------------
__global__ void loss_rows_kernel(const int* __restrict__ rel,
                                 float* __restrict__ out, int out_size) {
    __shared__ float red[256];
    __shared__ float rc[256];
    int i = blockIdx.x, j = threadIdx.x;
    int ri = rel[i];
    int rj = rel[j];
    float s1 = 0.f, s2 = 0.f;
#pragma unroll
    for (int p = 0; p < 4; p++) {
        s1 += g_simp[p * BATCH * TWOB + i * TWOB + j];
        s2 += g_simp[p * BATCH * TWOB + i * TWOB + BATCH + j];
    }
    float e1 = expf(s1 * INV_TEMP);
    float e2 = expf(s2 * INV_TEMP);
    int diff = ri - rj; if (diff < 0) diff = -diff;
    bool isneg = diff > SLICE_RANGE;
    bool ispos = (diff <= SLICE_RANGE) && (j != i);

    red[j] = (isneg ? e1 : 0.f) + e2;
    __syncthreads();
    for (int o = 128; o > 0; o >>= 1) {
        if (j < o) red[j] += red[j + o];
        __syncthreads();
    }
    float neg_sum = red[0];
    __syncthreads();

    red[j] = ispos ? (logf(e1 + neg_sum) - s1 * INV_TEMP) : 0.f;
    rc[j]  = ispos ? 1.f : 0.f;
    __syncthreads();
    for (int o = 128; o > 0; o >>= 1) {
        if (j < o) { red[j] += red[j + o]; rc[j] += rc[j + o]; }
        __syncthreads();
    }
    if (j == 0) {
        float cnt = rc[0];
        g_lossb[i] = (cnt > 0.f) ? (red[0] / cnt) : 0.f;
        g_cntd[i]  = (cnt > 0.f) ? 1.f : 0.f;
    }

    __threadfence();
    __shared__ unsigned ticket;
    if (j == 0) ticket = atomicAdd(&g_c2, 1u);
    __syncthreads();
    if (ticket == BATCH - 1) {
        if (j == 0) g_c2 = 0;   // reset for next graph replay
        __threadfence();
        red[j] = g_lossb[j];
        rc[j]  = g_cntd[j];
        __syncthreads();
        for (int o = 128; o > 0; o >>= 1) {
            if (j < o) { red[j] += red[j + o]; rc[j] += rc[j + o]; }
            __syncthreads();
        }
        if (j == 0) {
            out[0] = red[0];
            if (out_size > 1) out[1] = rc[0];
        }
    }
}

// ---------------------------------------------------------------------------
extern "C" void kernel_launch(void* const* d_in, const int* in_sizes, int n_in,
                              void* d_out, int out_size) {
    const float* z0    = (const float*)d_in[0];
    const float* z1    = (const float*)d_in[1];
    const int*   rel0  = (const int*)d_in[2];
    const float* W1    = (const float*)d_in[4];
    const float* b1    = (const float*)d_in[5];
    const float* gamma = (const float*)d_in[6];
    const float* beta  = (const float*)d_in[7];
    const float* W2    = (const float*)d_in[8];
    const float* b2    = (const float*)d_in[9];

    void *pb_, *w1b_, *w2b_, *hp_, *hb_, *zp_, *znb_, *simp_;
    cudaGetSymbolAddress(&pb_,  g_pb);
    cudaGetSymbolAddress(&w1b_, g_W1b);
    cudaGetSymbolAddress(&w2b_, g_W2b);
    cudaGetSymbolAddress(&hp_,  g_hp);
    cudaGetSymbolAddress(&hb_,  g_hb);
    cudaGetSymbolAddress(&zp_,  g_zp);
    cudaGetSymbolAddress(&znb_, g_znb);
    cudaGetSymbolAddress(&simp_, g_simp);

    // 1) pool + weight conversion
    prep_kernel<<<POOL_BLOCKS + CVT_BLOCKS, 256>>>(z0, z1, W1, W2);
    // 2) GEMM1: h = p @ W1^T + b1, split-K=2 -> 512 CTAs
    gemm_kernel<<<dim3(DIM / 64, TWOB / 64, 2), 128>>>(
        (const bf16*)pb_, (const bf16*)w1b_, (float*)hp_, b1,
        DIM, DIM, DIM / 2, TWOB);
    // 3) BN stats + fused finalize (last-ticket block)
    bn_stats_kernel<<<dim3(8, 32), 256>>>(gamma, beta);
    // 4) coalesced BN apply + ReLU -> bf16
    bn_apply_kernel<<<(TWOB * DIM / 4) / 256, 256>>>();
    // 5) GEMM2: z = hb @ W2^T + b2, split-K=2 -> 512 CTAs
    gemm_kernel<<<dim3(DIM / 64, TWOB / 64, 2), 128>>>(
        (const bf16*)hb_, (const bf16*)w2b_, (float*)zp_, b2,
        DIM, DIM, DIM / 2, TWOB);
    // 6) row normalize (combine partials) -> bf16
    rownorm_kernel<<<TWOB, 256>>>();
    // 7) sim partials: 64x64 tiles, split-K=4 -> 128 CTAs
    gemm_kernel<<<dim3(TWOB / 64, BATCH / 64, 4), 128>>>(
        (const bf16*)znb_, (const bf16*)znb_, (float*)simp_, nullptr,
        TWOB, DIM, DIM / 4, BATCH);
    // 8) per-row loss + fused deterministic finalize
    loss_rows_kernel<<<BATCH, 256>>>(rel0, (float*)d_out, out_size);
}

// round 13
// speedup vs baseline: 1.9892x; 1.9786x over previous
#include <cuda_runtime.h>
#include <cuda_bf16.h>
#include <math.h>

#define BATCH 256
#define TWOB 512
#define DIM 2048
#define HW 64
#define INV_TEMP 10.0f
#define BN_EPS 1e-5f
#define COS_EPS 1e-8f
#define SLICE_RANGE 2

typedef __nv_bfloat16 bf16;

// ---- scratch (device globals: no allocations allowed) ----
__device__ bf16  g_pb[TWOB * DIM];         // pooled, bf16
__device__ bf16  g_W1b[DIM * DIM];
__device__ bf16  g_W2b[DIM * DIM];
__device__ float g_hp[2 * TWOB * DIM];     // GEMM1 split-K partials
__device__ float g_ps[DIM * 32];           // bn partial sums  [col][chunk]
__device__ float g_pq[DIM * 32];           // bn partial sumsq [col][chunk]
__device__ float g_ga[DIM];                // gamma * istd
__device__ float g_be[DIM];                // beta - mu * ga
__device__ bf16  g_hb[TWOB * DIM];         // BN+ReLU, bf16
__device__ float g_zp[2 * TWOB * DIM];     // GEMM2 split-K partials
__device__ bf16  g_znb[TWOB * DIM];        // normalized rows, bf16
__device__ float g_simp[4 * BATCH * TWOB]; // sim split-K partials
__device__ float g_lossb[BATCH];
__device__ float g_cntd[BATCH];
__device__ unsigned g_c2 = 0;              // loss completion counter

__device__ __forceinline__ unsigned smem_u32(const void* p) {
    return (unsigned)__cvta_generic_to_shared(p);
}

// ---------------------------------------------------------------------------
// 1) prep: spatial mean pool (block range A) + weight f32->bf16 (block range B)
// ---------------------------------------------------------------------------
#define POOL_BLOCKS ((TWOB * DIM / 2) / 8)          // 65536
#define CVT_BLOCKS  ((2 * DIM * DIM / 4) / 256)     // 8192

__global__ void prep_kernel(const float* __restrict__ z0,
                            const float* __restrict__ z1,
                            const float* __restrict__ W1,
                            const float* __restrict__ W2) {
    if (blockIdx.x < POOL_BLOCKS) {
        int gt   = blockIdx.x * 256 + threadIdx.x;
        int warp = gt >> 5;
        int lane = gt & 31;
        int ch   = warp * 2 + (lane >> 4);
        const float* src = (ch < BATCH * DIM)
                             ? z0 + (size_t)ch * HW
                             : z1 + (size_t)(ch - BATCH * DIM) * HW;
        float4 v = ((const float4*)src)[lane & 15];
        float s = (v.x + v.y) + (v.z + v.w);
#pragma unroll
        for (int o = 8; o > 0; o >>= 1)
            s += __shfl_xor_sync(0xffffffffu, s, o);
        if ((lane & 15) == 0) g_pb[ch] = __float2bfloat16(s * (1.0f / 64.0f));
    } else {
        const int NPER = DIM * DIM / 4;
        int i = (blockIdx.x - POOL_BLOCKS) * 256 + threadIdx.x;
        const float* src;
        bf16* dst;
        int j;
        if (i < NPER) { src = W1; dst = g_W1b; j = i; }
        else          { src = W2; dst = g_W2b; j = i - NPER; }
        float4 v = ((const float4*)src)[j];
        ((__nv_bfloat162*)dst)[j * 2]     = __floats2bfloat162_rn(v.x, v.y);
        ((__nv_bfloat162*)dst)[j * 2 + 1] = __floats2bfloat162_rn(v.z, v.w);
    }
}

// ---------------------------------------------------------------------------
// 2) bf16 GEMM: C[M,N] = A[M,K]*B[N,K]^T (+bias). 64x64 tile, 4 warps (2x2),
//    warp tile 32x32. 3-stage cp.async pipeline, ldmatrix.x4 fragments.
//    blockIdx.z = split-K chunk, writes into partial buffer z*Mtot*N.
// ---------------------------------------------------------------------------
#define BK 32
#define SPAD 40   // bf16 per smem row (80B): conflict-free ldmatrix

__global__ void __launch_bounds__(128, 4) gemm_kernel(
    const bf16* __restrict__ A, const bf16* __restrict__ Bm,
    float* __restrict__ C, const float* __restrict__ bias,
    int N, int K, int kChunk, int Mtot) {
    constexpr int BM = 64, BN = 64, TPB = 128;
    __shared__ bf16 As[3][BM * SPAD];
    __shared__ bf16 Bs[3][BN * SPAD];

    const int tid  = threadIdx.x;
    const int warp = tid >> 5;
    const int lane = tid & 31;
    const int wm = warp >> 1;
    const int wn = warp & 1;
    const int rowBase = blockIdx.y * BM;
    const int colBase = blockIdx.x * BN;
    const int kOff    = blockIdx.z * kChunk;
    float* Cout = C + (size_t)blockIdx.z * Mtot * N;

    const bf16* Ag = A + (size_t)rowBase * K + kOff;
    const bf16* Bg = Bm + (size_t)colBase * K + kOff;

    auto loadStage = [&](int st, int it) {
        int kb = it * BK;
#pragma unroll
        for (int c = tid; c < BM * 4; c += TPB) {
            int r = c >> 2, chk = c & 3;
            unsigned sa = smem_u32(&As[st][r * SPAD + chk * 8]);
            asm volatile("cp.async.cg.shared.global [%0], [%1], 16;\n"
                         :: "r"(sa), "l"(Ag + (size_t)r * K + kb + chk * 8));
        }
#pragma unroll
        for (int c = tid; c < BN * 4; c += TPB) {
            int r = c >> 2, chk = c & 3;
            unsigned sa = smem_u32(&Bs[st][r * SPAD + chk * 8]);
            asm volatile("cp.async.cg.shared.global [%0], [%1], 16;\n"
                         :: "r"(sa), "l"(Bg + (size_t)r * K + kb + chk * 8));
        }
        asm volatile("cp.async.commit_group;\n");
    };

    float acc[2][4][4];
#pragma unroll
    for (int i = 0; i < 2; i++)
#pragma unroll
        for (int j = 0; j < 4; j++)
#pragma unroll
            for (int k = 0; k < 4; k++) acc[i][j][k] = 0.f;

    const int NIT = kChunk / BK;
    loadStage(0, 0);
    loadStage(1, 1);

    const int arow = lane & 15;
    const int acol = (lane >> 4) * 8;

    for (int it = 0; it < NIT; ++it) {
        asm volatile("cp.async.wait_group 1;\n" ::: "memory");
        __syncthreads();
        if (it + 2 < NIT) loadStage((it + 2) % 3, it + 2);
        else asm volatile("cp.async.commit_group;\n");
        const int buf = it % 3;

#pragma unroll
        for (int ks = 0; ks < 2; ++ks) {
            unsigned afr[2][4], bfr[2][4];
#pragma unroll
            for (int mt = 0; mt < 2; mt++) {
                unsigned sa = smem_u32(
                    &As[buf][(wm * 32 + mt * 16 + arow) * SPAD + acol + ks * 16]);
                asm volatile(
                    "ldmatrix.sync.aligned.m8n8.x4.shared.b16 {%0,%1,%2,%3}, [%4];\n"
                    : "=r"(afr[mt][0]), "=r"(afr[mt][1]),
                      "=r"(afr[mt][2]), "=r"(afr[mt][3]) : "r"(sa));
            }
#pragma unroll
            for (int np = 0; np < 2; np++) {
                unsigned sa = smem_u32(
                    &Bs[buf][(wn * 32 + np * 16 + arow) * SPAD + acol + ks * 16]);
                asm volatile(
                    "ldmatrix.sync.aligned.m8n8.x4.shared.b16 {%0,%1,%2,%3}, [%4];\n"
                    : "=r"(bfr[np][0]), "=r"(bfr[np][1]),
                      "=r"(bfr[np][2]), "=r"(bfr[np][3]) : "r"(sa));
            }
#pragma unroll
            for (int mt = 0; mt < 2; mt++)
#pragma unroll
                for (int nt = 0; nt < 4; nt++) {
                    asm volatile(
                        "mma.sync.aligned.m16n8k16.row.col.f32.bf16.bf16.f32 "
                        "{%0,%1,%2,%3}, {%4,%5,%6,%7}, {%8,%9}, {%0,%1,%2,%3};\n"
                        : "+f"(acc[mt][nt][0]), "+f"(acc[mt][nt][1]),
                          "+f"(acc[mt][nt][2]), "+f"(acc[mt][nt][3])
                        : "r"(afr[mt][0]), "r"(afr[mt][1]),
                          "r"(afr[mt][2]), "r"(afr[mt][3]),
                          "r"(bfr[nt >> 1][nt & 1]), "r"(bfr[nt >> 1][2 + (nt & 1)]));
                }
        }
        __syncthreads();
    }

    const int g  = lane >> 2;
    const int t4 = lane & 3;
    const bool addb = (bias != nullptr) && (blockIdx.z == 0);
#pragma unroll
    for (int mt = 0; mt < 2; mt++) {
        int r0 = rowBase + wm * 32 + mt * 16 + g;
#pragma unroll
        for (int nt = 0; nt < 4; nt++) {
            int c0 = colBase + wn * 32 + nt * 8 + t4 * 2;
            float bx = addb ? bias[c0] : 0.f;
            float by = addb ? bias[c0 + 1] : 0.f;
            *(float2*)&Cout[(size_t)r0 * N + c0] =
                make_float2(acc[mt][nt][0] + bx, acc[mt][nt][1] + by);
            *(float2*)&Cout[(size_t)(r0 + 8) * N + c0] =
                make_float2(acc[mt][nt][2] + bx, acc[mt][nt][3] + by);
        }
    }
}

// ---------------------------------------------------------------------------
// 3) BN partial stats over combined h: grid (8, 32); 16 rows x 256 cols.
//    Partials stored TRANSPOSED: g_ps[col*32 + chunk] for coalesced finalize.
// ---------------------------------------------------------------------------
__global__ void bn_stats_kernel() {
    int col = blockIdx.x * 256 + threadIdx.x;
    int r0  = blockIdx.y * 16;
    float s = 0.f, q = 0.f;
#pragma unroll
    for (int r = 0; r < 16; r++) {
        size_t i = (size_t)(r0 + r) * DIM + col;
        float v = g_hp[i] + g_hp[TWOB * (size_t)DIM + i];
        s += v; q += v * v;
    }
    g_ps[col * 32 + blockIdx.y] = s;
    g_pq[col * 32 + blockIdx.y] = q;
}

// ---------------------------------------------------------------------------
// 4a) BN finalize: warp per column, lane per chunk — coalesced (256 blocks)
// ---------------------------------------------------------------------------
__global__ void bn_finalize_kernel(const float* __restrict__ gamma,
                                   const float* __restrict__ beta) {
    int col  = (blockIdx.x * 256 + threadIdx.x) >> 5;   // 0..DIM-1
    int lane = threadIdx.x & 31;
    float s = g_ps[col * 32 + lane];
    float q = g_pq[col * 32 + lane];
#pragma unroll
    for (int o = 16; o > 0; o >>= 1) {
        s += __shfl_xor_sync(0xffffffffu, s, o);
        q += __shfl_xor_sync(0xffffffffu, q, o);
    }
    if (lane == 0) {
        float mu   = s * (1.f / TWOB);
        float var  = q * (1.f / TWOB) - mu * mu;
        float istd = rsqrtf(var + BN_EPS);
        float ga = gamma[col] * istd;
        g_ga[col] = ga;
        g_be[col] = beta[col] - mu * ga;
    }
}

// ---------------------------------------------------------------------------
// 4b) BN apply + ReLU -> bf16: fully coalesced float4 walk (1024 blocks)
// ---------------------------------------------------------------------------
__global__ void bn_apply_kernel() {
    int i4 = blockIdx.x * 256 + threadIdx.x;      // float4 index
    int c4 = i4 & (DIM / 4 - 1);                  // float4 index within row
    float4 a = ((const float4*)g_hp)[i4];
    float4 b = ((const float4*)(g_hp + TWOB * (size_t)DIM))[i4];
    float4 ga = ((const float4*)g_ga)[c4];
    float4 be = ((const float4*)g_be)[c4];
    float v0 = fmaxf((a.x + b.x) * ga.x + be.x, 0.f);
    float v1 = fmaxf((a.y + b.y) * ga.y + be.y, 0.f);
    float v2 = fmaxf((a.z + b.z) * ga.z + be.z, 0.f);
    float v3 = fmaxf((a.w + b.w) * ga.w + be.w, 0.f);
    __nv_bfloat162* dst = (__nv_bfloat162*)g_hb;
    dst[i4 * 2]     = __floats2bfloat162_rn(v0, v1);
    dst[i4 * 2 + 1] = __floats2bfloat162_rn(v2, v3);
}

// ---------------------------------------------------------------------------
// 5) row L2 normalize (combines 2 z partials) -> bf16
// ---------------------------------------------------------------------------
__global__ void rownorm_kernel() {
    __shared__ float red[256];
    int r = blockIdx.x, tid = threadIdx.x;
    const float4* p0 = (const float4*)(g_zp + (size_t)r * DIM);
    const float4* p1 = (const float4*)(g_zp + TWOB * (size_t)DIM + (size_t)r * DIM);
    float4 a0 = p0[tid], a1 = p1[tid];
    float4 b0 = p0[tid + 256], b1 = p1[tid + 256];
    float4 a = make_float4(a0.x + a1.x, a0.y + a1.y, a0.z + a1.z, a0.w + a1.w);
    float4 b = make_float4(b0.x + b1.x, b0.y + b1.y, b0.z + b1.z, b0.w + b1.w);
    float s = a.x * a.x + a.y * a.y + a.z * a.z + a.w * a.w
            + b.x * b.x + b.y * b.y + b.z * b.z + b.w * b.w;
    red[tid] = s;
    __syncthreads();
    for (int o = 128; o > 0; o >>= 1) {
        if (tid < o) red[tid] += red[tid + o];
        __syncthreads();
    }
    float inv = 1.f / fmaxf(sqrtf(red[0]), COS_EPS);
    __nv_bfloat162* dst = (__nv_bfloat162*)(g_znb + (size_t)r * DIM);
    dst[tid * 2]             = __floats2bfloat162_rn(a.x * inv, a.y * inv);
    dst[tid * 2 + 1]         = __floats2bfloat162_rn(a.z * inv, a.w * inv);
    dst[(tid + 256) * 2]     = __floats2bfloat162_rn(b.x * inv, b.y * inv);
    dst[(tid + 256) * 2 + 1] = __floats2bfloat162_rn(b.z * inv, b.w * inv);
}

// ---------------------------------------------------------------------------
// 6) per-row contrastive loss (sums 4 K-partials) + fused final reduce
// ---------------------------------------------------------------------------
__global__ void loss_rows_kernel(const int* __restrict__ rel,
                                 float* __restrict__ out, int out_size) {
    __shared__ float red[256];
    __shared__ float rc[256];
    int i = blockIdx.x, j = threadIdx.x;
    int ri = rel[i];
    int rj = rel[j];
    float s1 = 0.f, s2 = 0.f;
#pragma unroll
    for (int p = 0; p < 4; p++) {
        s1 += g_simp[p * BATCH * TWOB + i * TWOB + j];
        s2 += g_simp[p * BATCH * TWOB + i * TWOB + BATCH + j];
    }
    float e1 = expf(s1 * INV_TEMP);
    float e2 = expf(s2 * INV_TEMP);
    int diff = ri - rj; if (diff < 0) diff = -diff;
    bool isneg = diff > SLICE_RANGE;
    bool ispos = (diff <= SLICE_RANGE) && (j != i);

    red[j] = (isneg ? e1 : 0.f) + e2;
    __syncthreads();
    for (int o = 128; o > 0; o >>= 1) {
        if (j < o) red[j] += red[j + o];
        __syncthreads();
    }
    float neg_sum = red[0];
    __syncthreads();

    red[j] = ispos ? (logf(e1 + neg_sum) - s1 * INV_TEMP) : 0.f;
    rc[j]  = ispos ? 1.f : 0.f;
    __syncthreads();
    for (int o = 128; o > 0; o >>= 1) {
        if (j < o) { red[j] += red[j + o]; rc[j] += rc[j + o]; }
        __syncthreads();
    }
    if (j == 0) {
        float cnt = rc[0];
        g_lossb[i] = (cnt > 0.f) ? (red[0] / cnt) : 0.f;
        g_cntd[i]  = (cnt > 0.f) ? 1.f : 0.f;
    }

    __threadfence();
    __shared__ unsigned ticket;
    if (j == 0) ticket = atomicAdd(&g_c2, 1u);
    __syncthreads();
    if (ticket == BATCH - 1) {
        if (j == 0) g_c2 = 0;   // reset for next graph replay
        __threadfence();
        red[j] = g_lossb[j];
        rc[j]  = g_cntd[j];
        __syncthreads();
        for (int o = 128; o > 0; o >>= 1) {
            if (j < o) { red[j] += red[j + o]; rc[j] += rc[j + o]; }
            __syncthreads();
        }
        if (j == 0) {
            out[0] = red[0];
            if (out_size > 1) out[1] = rc[0];
        }
    }
}

// ---------------------------------------------------------------------------
extern "C" void kernel_launch(void* const* d_in, const int* in_sizes, int n_in,
                              void* d_out, int out_size) {
    const float* z0    = (const float*)d_in[0];
    const float* z1    = (const float*)d_in[1];
    const int*   rel0  = (const int*)d_in[2];
    const float* W1    = (const float*)d_in[4];
    const float* b1    = (const float*)d_in[5];
    const float* gamma = (const float*)d_in[6];
    const float* beta  = (const float*)d_in[7];
    const float* W2    = (const float*)d_in[8];
    const float* b2    = (const float*)d_in[9];

    void *pb_, *w1b_, *w2b_, *hp_, *hb_, *zp_, *znb_, *simp_;
    cudaGetSymbolAddress(&pb_,  g_pb);
    cudaGetSymbolAddress(&w1b_, g_W1b);
    cudaGetSymbolAddress(&w2b_, g_W2b);
    cudaGetSymbolAddress(&hp_,  g_hp);
    cudaGetSymbolAddress(&hb_,  g_hb);
    cudaGetSymbolAddress(&zp_,  g_zp);
    cudaGetSymbolAddress(&znb_, g_znb);
    cudaGetSymbolAddress(&simp_, g_simp);

    // 1) pool + weight conversion
    prep_kernel<<<POOL_BLOCKS + CVT_BLOCKS, 256>>>(z0, z1, W1, W2);
    // 2) GEMM1: h = p @ W1^T + b1, split-K=2 -> 512 CTAs
    gemm_kernel<<<dim3(DIM / 64, TWOB / 64, 2), 128>>>(
        (const bf16*)pb_, (const bf16*)w1b_, (float*)hp_, b1,
        DIM, DIM, DIM / 2, TWOB);
    // 3) BN stats over combined partials (transposed partial layout)
    bn_stats_kernel<<<dim3(8, 32), 256>>>();
    // 4) BN finalize (coalesced warp/column) then coalesced apply
    bn_finalize_kernel<<<DIM / 8, 256>>>(gamma, beta);
    bn_apply_kernel<<<(TWOB * DIM / 4) / 256, 256>>>();
    // 5) GEMM2: z = hb @ W2^T + b2, split-K=2 -> 512 CTAs
    gemm_kernel<<<dim3(DIM / 64, TWOB / 64, 2), 128>>>(
        (const bf16*)hb_, (const bf16*)w2b_, (float*)zp_, b2,
        DIM, DIM, DIM / 2, TWOB);
    // 6) row normalize (combine partials) -> bf16
    rownorm_kernel<<<TWOB, 256>>>();
    // 7) sim partials: 64x64 tiles, split-K=4 -> 128 CTAs
    gemm_kernel<<<dim3(TWOB / 64, BATCH / 64, 4), 128>>>(
        (const bf16*)znb_, (const bf16*)znb_, (float*)simp_, nullptr,
        TWOB, DIM, DIM / 4, BATCH);
    // 8) per-row loss + fused deterministic finalize
    loss_rows_kernel<<<BATCH, 256>>>(rel0, (float*)d_out, out_size);
}

// round 14
// speedup vs baseline: 2.1869x; 1.0994x over previous
#include <cuda_runtime.h>
#include <cuda_bf16.h>
#include <math.h>

#define BATCH 256
#define TWOB 512
#define DIM 2048
#define HW 64
#define INV_TEMP 10.0f
#define BN_EPS 1e-5f
#define COS_EPS 1e-8f
#define SLICE_RANGE 2

typedef __nv_bfloat16 bf16;

// ---- scratch (device globals: no allocations allowed) ----
__device__ bf16  g_pb[TWOB * DIM];         // pooled, bf16
__device__ bf16  g_W1b[DIM * DIM];
__device__ bf16  g_W2b[DIM * DIM];
__device__ float g_hp[2 * TWOB * DIM];     // GEMM1 split-K partials
__device__ float g_ps[DIM * 32];           // bn partial sums  [col][chunk]
__device__ float g_pq[DIM * 32];           // bn partial sumsq [col][chunk]
__device__ float g_ga[DIM];                // gamma * istd
__device__ float g_be[DIM];                // beta - mu * ga
__device__ bf16  g_hb[TWOB * DIM];         // BN+ReLU, bf16
__device__ float g_zp[2 * TWOB * DIM];     // GEMM2 split-K partials
__device__ bf16  g_znb[TWOB * DIM];        // normalized rows, bf16
__device__ float g_simp[4 * BATCH * TWOB]; // sim split-K partials
__device__ float g_lossb[BATCH];
__device__ float g_cntd[BATCH];
__device__ unsigned g_c2 = 0;              // loss completion counter

__device__ __forceinline__ unsigned smem_u32(const void* p) {
    return (unsigned)__cvta_generic_to_shared(p);
}

// ---------------------------------------------------------------------------
// 1) prep: spatial mean pool (block range A) + weight f32->bf16 (block range B)
//    Pool v2: 8 channels per warp, 4 independent coalesced LDG.128 per lane
//    (MLP=4) — each channel-pair load is 512B contiguous per warp.
// ---------------------------------------------------------------------------
#define POOL_BLOCKS ((TWOB * DIM) / 64)             // 16384 (64 ch per block)
#define CVT_BLOCKS  ((2 * DIM * DIM / 4) / 256)     // 8192

__global__ void prep_kernel(const float* __restrict__ z0,
                            const float* __restrict__ z1,
                            const float* __restrict__ W1,
                            const float* __restrict__ W2) {
    if (blockIdx.x < POOL_BLOCKS) {
        int warp = (blockIdx.x * 256 + threadIdx.x) >> 5;  // global warp id
        int lane = threadIdx.x & 31;
        int chBase = warp * 8;                 // 8 channels per warp
        int half = lane >> 4;                  // 0 or 1 within pair
        int f4   = lane & 15;                  // float4 index within channel
        float4 v[4];
#pragma unroll
        for (int i = 0; i < 4; i++) {
            int ch = chBase + 2 * i + half;
            const float* src = (ch < BATCH * DIM)
                                 ? z0 + (size_t)ch * HW
                                 : z1 + (size_t)(ch - BATCH * DIM) * HW;
            v[i] = ((const float4*)src)[f4];
        }
#pragma unroll
        for (int i = 0; i < 4; i++) {
            float s = (v[i].x + v[i].y) + (v[i].z + v[i].w);
#pragma unroll
            for (int o = 8; o > 0; o >>= 1)
                s += __shfl_xor_sync(0xffffffffu, s, o);
            if (f4 == 0)
                g_pb[chBase + 2 * i + half] = __float2bfloat16(s * (1.0f / 64.0f));
        }
    } else {
        const int NPER = DIM * DIM / 4;
        int i = (blockIdx.x - POOL_BLOCKS) * 256 + threadIdx.x;
        const float* src;
        bf16* dst;
        int j;
        if (i < NPER) { src = W1; dst = g_W1b; j = i; }
        else          { src = W2; dst = g_W2b; j = i - NPER; }
        float4 v = ((const float4*)src)[j];
        ((__nv_bfloat162*)dst)[j * 2]     = __floats2bfloat162_rn(v.x, v.y);
        ((__nv_bfloat162*)dst)[j * 2 + 1] = __floats2bfloat162_rn(v.z, v.w);
    }
}

// ---------------------------------------------------------------------------
// 2) bf16 GEMM: C[M,N] = A[M,K]*B[N,K]^T (+bias). 64x64 tile, 4 warps (2x2),
//    warp tile 32x32. 3-stage cp.async pipeline, ldmatrix.x4 fragments.
//    blockIdx.z = split-K chunk, writes into partial buffer z*Mtot*N.
// ---------------------------------------------------------------------------
#define BK 32
#define SPAD 40   // bf16 per smem row (80B): conflict-free ldmatrix

__global__ void __launch_bounds__(128, 4) gemm_kernel(
    const bf16* __restrict__ A, const bf16* __restrict__ Bm,
    float* __restrict__ C, const float* __restrict__ bias,
    int N, int K, int kChunk, int Mtot) {
    constexpr int BM = 64, BN = 64, TPB = 128;
    __shared__ bf16 As[3][BM * SPAD];
    __shared__ bf16 Bs[3][BN * SPAD];

    const int tid  = threadIdx.x;
    const int warp = tid >> 5;
    const int lane = tid & 31;
    const int wm = warp >> 1;
    const int wn = warp & 1;
    const int rowBase = blockIdx.y * BM;
    const int colBase = blockIdx.x * BN;
    const int kOff    = blockIdx.z * kChunk;
    float* Cout = C + (size_t)blockIdx.z * Mtot * N;

    const bf16* Ag = A + (size_t)rowBase * K + kOff;
    const bf16* Bg = Bm + (size_t)colBase * K + kOff;

    auto loadStage = [&](int st, int it) {
        int kb = it * BK;
#pragma unroll
        for (int c = tid; c < BM * 4; c += TPB) {
            int r = c >> 2, chk = c & 3;
            unsigned sa = smem_u32(&As[st][r * SPAD + chk * 8]);
            asm volatile("cp.async.cg.shared.global [%0], [%1], 16;\n"
                         :: "r"(sa), "l"(Ag + (size_t)r * K + kb + chk * 8));
        }
#pragma unroll
        for (int c = tid; c < BN * 4; c += TPB) {
            int r = c >> 2, chk = c & 3;
            unsigned sa = smem_u32(&Bs[st][r * SPAD + chk * 8]);
            asm volatile("cp.async.cg.shared.global [%0], [%1], 16;\n"
                         :: "r"(sa), "l"(Bg + (size_t)r * K + kb + chk * 8));
        }
        asm volatile("cp.async.commit_group;\n");
    };

    float acc[2][4][4];
#pragma unroll
    for (int i = 0; i < 2; i++)
#pragma unroll
        for (int j = 0; j < 4; j++)
#pragma unroll
            for (int k = 0; k < 4; k++) acc[i][j][k] = 0.f;

    const int NIT = kChunk / BK;
    loadStage(0, 0);
    loadStage(1, 1);

    const int arow = lane & 15;
    const int acol = (lane >> 4) * 8;

    for (int it = 0; it < NIT; ++it) {
        asm volatile("cp.async.wait_group 1;\n" ::: "memory");
        __syncthreads();
        if (it + 2 < NIT) loadStage((it + 2) % 3, it + 2);
        else asm volatile("cp.async.commit_group;\n");
        const int buf = it % 3;

#pragma unroll
        for (int ks = 0; ks < 2; ++ks) {
            unsigned afr[2][4], bfr[2][4];
#pragma unroll
            for (int mt = 0; mt < 2; mt++) {
                unsigned sa = smem_u32(
                    &As[buf][(wm * 32 + mt * 16 + arow) * SPAD + acol + ks * 16]);
                asm volatile(
                    "ldmatrix.sync.aligned.m8n8.x4.shared.b16 {%0,%1,%2,%3}, [%4];\n"
                    : "=r"(afr[mt][0]), "=r"(afr[mt][1]),
                      "=r"(afr[mt][2]), "=r"(afr[mt][3]) : "r"(sa));
            }
#pragma unroll
            for (int np = 0; np < 2; np++) {
                unsigned sa = smem_u32(
                    &Bs[buf][(wn * 32 + np * 16 + arow) * SPAD + acol + ks * 16]);
                asm volatile(
                    "ldmatrix.sync.aligned.m8n8.x4.shared.b16 {%0,%1,%2,%3}, [%4];\n"
                    : "=r"(bfr[np][0]), "=r"(bfr[np][1]),
                      "=r"(bfr[np][2]), "=r"(bfr[np][3]) : "r"(sa));
            }
#pragma unroll
            for (int mt = 0; mt < 2; mt++)
#pragma unroll
                for (int nt = 0; nt < 4; nt++) {
                    asm volatile(
                        "mma.sync.aligned.m16n8k16.row.col.f32.bf16.bf16.f32 "
                        "{%0,%1,%2,%3}, {%4,%5,%6,%7}, {%8,%9}, {%0,%1,%2,%3};\n"
                        : "+f"(acc[mt][nt][0]), "+f"(acc[mt][nt][1]),
                          "+f"(acc[mt][nt][2]), "+f"(acc[mt][nt][3])
                        : "r"(afr[mt][0]), "r"(afr[mt][1]),
                          "r"(afr[mt][2]), "r"(afr[mt][3]),
                          "r"(bfr[nt >> 1][nt & 1]), "r"(bfr[nt >> 1][2 + (nt & 1)]));
                }
        }
        __syncthreads();
    }

    const int g  = lane >> 2;
    const int t4 = lane & 3;
    const bool addb = (bias != nullptr) && (blockIdx.z == 0);
#pragma unroll
    for (int mt = 0; mt < 2; mt++) {
        int r0 = rowBase + wm * 32 + mt * 16 + g;
#pragma unroll
        for (int nt = 0; nt < 4; nt++) {
            int c0 = colBase + wn * 32 + nt * 8 + t4 * 2;
            float bx = addb ? bias[c0] : 0.f;
            float by = addb ? bias[c0 + 1] : 0.f;
            *(float2*)&Cout[(size_t)r0 * N + c0] =
                make_float2(acc[mt][nt][0] + bx, acc[mt][nt][1] + by);
            *(float2*)&Cout[(size_t)(r0 + 8) * N + c0] =
                make_float2(acc[mt][nt][2] + bx, acc[mt][nt][3] + by);
        }
    }
}

// ---------------------------------------------------------------------------
// 3) BN partial stats over combined h: grid (8, 32); 16 rows x 256 cols.
//    Partials stored TRANSPOSED: g_ps[col*32 + chunk] for coalesced finalize.
// ---------------------------------------------------------------------------
__global__ void bn_stats_kernel() {
    int col = blockIdx.x * 256 + threadIdx.x;
    int r0  = blockIdx.y * 16;
    float s = 0.f, q = 0.f;
#pragma unroll
    for (int r = 0; r < 16; r++) {
        size_t i = (size_t)(r0 + r) * DIM + col;
        float v = g_hp[i] + g_hp[TWOB * (size_t)DIM + i];
        s += v; q += v * v;
    }
    g_ps[col * 32 + blockIdx.y] = s;
    g_pq[col * 32 + blockIdx.y] = q;
}

// ---------------------------------------------------------------------------
// 4a) BN finalize: warp per column, lane per chunk — coalesced (256 blocks)
// ---------------------------------------------------------------------------
__global__ void bn_finalize_kernel(const float* __restrict__ gamma,
                                   const float* __restrict__ beta) {
    int col  = (blockIdx.x * 256 + threadIdx.x) >> 5;   // 0..DIM-1
    int lane = threadIdx.x & 31;
    float s = g_ps[col * 32 + lane];
    float q = g_pq[col * 32 + lane];
#pragma unroll
    for (int o = 16; o > 0; o >>= 1) {
        s += __shfl_xor_sync(0xffffffffu, s, o);
        q += __shfl_xor_sync(0xffffffffu, q, o);
    }
    if (lane == 0) {
        float mu   = s * (1.f / TWOB);
        float var  = q * (1.f / TWOB) - mu * mu;
        float istd = rsqrtf(var + BN_EPS);
        float ga = gamma[col] * istd;
        g_ga[col] = ga;
        g_be[col] = beta[col] - mu * ga;
    }
}

// ---------------------------------------------------------------------------
// 4b) BN apply + ReLU -> bf16: fully coalesced float4 walk (1024 blocks)
// ---------------------------------------------------------------------------
__global__ void bn_apply_kernel() {
    int i4 = blockIdx.x * 256 + threadIdx.x;      // float4 index
    int c4 = i4 & (DIM / 4 - 1);                  // float4 index within row
    float4 a = ((const float4*)g_hp)[i4];
    float4 b = ((const float4*)(g_hp + TWOB * (size_t)DIM))[i4];
    float4 ga = ((const float4*)g_ga)[c4];
    float4 be = ((const float4*)g_be)[c4];
    float v0 = fmaxf((a.x + b.x) * ga.x + be.x, 0.f);
    float v1 = fmaxf((a.y + b.y) * ga.y + be.y, 0.f);
    float v2 = fmaxf((a.z + b.z) * ga.z + be.z, 0.f);
    float v3 = fmaxf((a.w + b.w) * ga.w + be.w, 0.f);
    __nv_bfloat162* dst = (__nv_bfloat162*)g_hb;
    dst[i4 * 2]     = __floats2bfloat162_rn(v0, v1);
    dst[i4 * 2 + 1] = __floats2bfloat162_rn(v2, v3);
}

// ---------------------------------------------------------------------------
// 5) row L2 normalize (combines 2 z partials) -> bf16
// ---------------------------------------------------------------------------
__global__ void rownorm_kernel() {
    __shared__ float red[256];
    int r = blockIdx.x, tid = threadIdx.x;
    const float4* p0 = (const float4*)(g_zp + (size_t)r * DIM);
    const float4* p1 = (const float4*)(g_zp + TWOB * (size_t)DIM + (size_t)r * DIM);
    float4 a0 = p0[tid], a1 = p1[tid];
    float4 b0 = p0[tid + 256], b1 = p1[tid + 256];
    float4 a = make_float4(a0.x + a1.x, a0.y + a1.y, a0.z + a1.z, a0.w + a1.w);
    float4 b = make_float4(b0.x + b1.x, b0.y + b1.y, b0.z + b1.z, b0.w + b1.w);
    float s = a.x * a.x + a.y * a.y + a.z * a.z + a.w * a.w
            + b.x * b.x + b.y * b.y + b.z * b.z + b.w * b.w;
    red[tid] = s;
    __syncthreads();
    for (int o = 128; o > 0; o >>= 1) {
        if (tid < o) red[tid] += red[tid + o];
        __syncthreads();
    }
    float inv = 1.f / fmaxf(sqrtf(red[0]), COS_EPS);
    __nv_bfloat162* dst = (__nv_bfloat162*)(g_znb + (size_t)r * DIM);
    dst[tid * 2]             = __floats2bfloat162_rn(a.x * inv, a.y * inv);
    dst[tid * 2 + 1]         = __floats2bfloat162_rn(a.z * inv, a.w * inv);
    dst[(tid + 256) * 2]     = __floats2bfloat162_rn(b.x * inv, b.y * inv);
    dst[(tid + 256) * 2 + 1] = __floats2bfloat162_rn(b.z * inv, b.w * inv);
}

// ---------------------------------------------------------------------------
// 6) per-row contrastive loss (sums 4 K-partials) + fused final reduce
// ---------------------------------------------------------------------------
__global__ void loss_rows_kernel(const int* __restrict__ rel,
                                 float* __restrict__ out, int out_size) {
    __shared__ float red[256];
    __shared__ float rc[256];
    int i = blockIdx.x, j = threadIdx.x;
    int ri = rel[i];
    int rj = rel[j];
    float s1 = 0.f, s2 = 0.f;
#pragma unroll
    for (int p = 0; p < 4; p++) {
        s1 += g_simp[p * BATCH * TWOB + i * TWOB + j];
        s2 += g_simp[p * BATCH * TWOB + i * TWOB + BATCH + j];
    }
    float e1 = expf(s1 * INV_TEMP);
    float e2 = expf(s2 * INV_TEMP);
    int diff = ri - rj; if (diff < 0) diff = -diff;
    bool isneg = diff > SLICE_RANGE;
    bool ispos = (diff <= SLICE_RANGE) && (j != i);

    red[j] = (isneg ? e1 : 0.f) + e2;
    __syncthreads();
    for (int o = 128; o > 0; o >>= 1) {
        if (j < o) red[j] += red[j + o];
        __syncthreads();
    }
    float neg_sum = red[0];
    __syncthreads();

    red[j] = ispos ? (logf(e1 + neg_sum) - s1 * INV_TEMP) : 0.f;
    rc[j]  = ispos ? 1.f : 0.f;
    __syncthreads();
    for (int o = 128; o > 0; o >>= 1) {
        if (j < o) { red[j] += red[j + o]; rc[j] += rc[j + o]; }
        __syncthreads();
    }
    if (j == 0) {
        float cnt = rc[0];
        g_lossb[i] = (cnt > 0.f) ? (red[0] / cnt) : 0.f;
        g_cntd[i]  = (cnt > 0.f) ? 1.f : 0.f;
    }

    __threadfence();
    __shared__ unsigned ticket;
    if (j == 0) ticket = atomicAdd(&g_c2, 1u);
    __syncthreads();
    if (ticket == BATCH - 1) {
        if (j == 0) g_c2 = 0;   // reset for next graph replay
        __threadfence();
        red[j] = g_lossb[j];
        rc[j]  = g_cntd[j];
        __syncthreads();
        for (int o = 128; o > 0; o >>= 1) {
            if (j < o) { red[j] += red[j + o]; rc[j] += rc[j + o]; }
            __syncthreads();
        }
        if (j == 0) {
            out[0] = red[0];
            if (out_size > 1) out[1] = rc[0];
        }
    }
}

// ---------------------------------------------------------------------------
extern "C" void kernel_launch(void* const* d_in, const int* in_sizes, int n_in,
                              void* d_out, int out_size) {
    const float* z0    = (const float*)d_in[0];
    const float* z1    = (const float*)d_in[1];
    const int*   rel0  = (const int*)d_in[2];
    const float* W1    = (const float*)d_in[4];
    const float* b1    = (const float*)d_in[5];
    const float* gamma = (const float*)d_in[6];
    const float* beta  = (const float*)d_in[7];
    const float* W2    = (const float*)d_in[8];
    const float* b2    = (const float*)d_in[9];

    void *pb_, *w1b_, *w2b_, *hp_, *hb_, *zp_, *znb_, *simp_;
    cudaGetSymbolAddress(&pb_,  g_pb);
    cudaGetSymbolAddress(&w1b_, g_W1b);
    cudaGetSymbolAddress(&w2b_, g_W2b);
    cudaGetSymbolAddress(&hp_,  g_hp);
    cudaGetSymbolAddress(&hb_,  g_hb);
    cudaGetSymbolAddress(&zp_,  g_zp);
    cudaGetSymbolAddress(&znb_, g_znb);
    cudaGetSymbolAddress(&simp_, g_simp);

    // 1) pool (MLP=4) + weight conversion
    prep_kernel<<<POOL_BLOCKS + CVT_BLOCKS, 256>>>(z0, z1, W1, W2);
    // 2) GEMM1: h = p @ W1^T + b1, split-K=2 -> 512 CTAs
    gemm_kernel<<<dim3(DIM / 64, TWOB / 64, 2), 128>>>(
        (const bf16*)pb_, (const bf16*)w1b_, (float*)hp_, b1,
        DIM, DIM, DIM / 2, TWOB);
    // 3) BN stats over combined partials (transposed partial layout)
    bn_stats_kernel<<<dim3(8, 32), 256>>>();
    // 4) BN finalize (coalesced warp/column) then coalesced apply
    bn_finalize_kernel<<<DIM / 8, 256>>>(gamma, beta);
    bn_apply_kernel<<<(TWOB * DIM / 4) / 256, 256>>>();
    // 5) GEMM2: z = hb @ W2^T + b2, split-K=2 -> 512 CTAs
    gemm_kernel<<<dim3(DIM / 64, TWOB / 64, 2), 128>>>(
        (const bf16*)hb_, (const bf16*)w2b_, (float*)zp_, b2,
        DIM, DIM, DIM / 2, TWOB);
    // 6) row normalize (combine partials) -> bf16
    rownorm_kernel<<<TWOB, 256>>>();
    // 7) sim partials: 64x64 tiles, split-K=4 -> 128 CTAs
    gemm_kernel<<<dim3(TWOB / 64, BATCH / 64, 4), 128>>>(
        (const bf16*)znb_, (const bf16*)znb_, (float*)simp_, nullptr,
        TWOB, DIM, DIM / 4, BATCH);
    // 8) per-row loss + fused deterministic finalize
    loss_rows_kernel<<<BATCH, 256>>>(rel0, (float*)d_out, out_size);
}

// round 15
// speedup vs baseline: 2.1920x; 1.0023x over previous
#include <cuda_runtime.h>
#include <cuda_bf16.h>
#include <math.h>

#define BATCH 256
#define TWOB 512
#define DIM 2048
#define HW 64
#define INV_TEMP 10.0f
#define BN_EPS 1e-5f
#define COS_EPS 1e-8f
#define SLICE_RANGE 2

typedef __nv_bfloat16 bf16;

// ---- scratch (device globals: no allocations allowed) ----
__device__ bf16  g_pb[TWOB * DIM];         // pooled, bf16
__device__ bf16  g_W1b[DIM * DIM];
__device__ bf16  g_W2b[DIM * DIM];
__device__ float g_hp[2 * TWOB * DIM];     // GEMM1 split-K partials
__device__ float g_ps[DIM * 32];           // bn partial sums  [col][chunk]
__device__ float g_pq[DIM * 32];           // bn partial sumsq [col][chunk]
__device__ float g_ga[DIM];                // gamma * istd
__device__ float g_be[DIM];                // beta - mu * ga
__device__ bf16  g_hb[TWOB * DIM];         // BN+ReLU, bf16
__device__ float g_zp[2 * TWOB * DIM];     // GEMM2 split-K partials
__device__ bf16  g_znb[TWOB * DIM];        // normalized rows, bf16
__device__ float g_simp[4 * BATCH * TWOB]; // sim split-K partials
__device__ float g_lossb[BATCH];
__device__ float g_cntd[BATCH];
__device__ unsigned g_c2 = 0;              // loss completion counter

__device__ __forceinline__ unsigned smem_u32(const void* p) {
    return (unsigned)__cvta_generic_to_shared(p);
}

// ---------------------------------------------------------------------------
// 1) prep: spatial mean pool (block range A) + weight f32->bf16 (block range B)
//    Pool v3: 16 channels per warp, 8 independent coalesced LDG.128 per lane
//    (MLP=8) — each channel-pair load is 512B contiguous per warp.
// ---------------------------------------------------------------------------
#define POOL_BLOCKS ((TWOB * DIM) / 128)            // 8192 (128 ch per block)
#define CVT_BLOCKS  ((2 * DIM * DIM / 4) / 256)     // 8192

__global__ void prep_kernel(const float* __restrict__ z0,
                            const float* __restrict__ z1,
                            const float* __restrict__ W1,
                            const float* __restrict__ W2) {
    if (blockIdx.x < POOL_BLOCKS) {
        int warp = (blockIdx.x * 256 + threadIdx.x) >> 5;  // global warp id
        int lane = threadIdx.x & 31;
        int chBase = warp * 16;                // 16 channels per warp
        int half = lane >> 4;                  // 0 or 1 within pair
        int f4   = lane & 15;                  // float4 index within channel
        float4 v[8];
#pragma unroll
        for (int i = 0; i < 8; i++) {
            int ch = chBase + 2 * i + half;
            const float* src = (ch < BATCH * DIM)
                                 ? z0 + (size_t)ch * HW
                                 : z1 + (size_t)(ch - BATCH * DIM) * HW;
            v[i] = ((const float4*)src)[f4];
        }
#pragma unroll
        for (int i = 0; i < 8; i++) {
            float s = (v[i].x + v[i].y) + (v[i].z + v[i].w);
#pragma unroll
            for (int o = 8; o > 0; o >>= 1)
                s += __shfl_xor_sync(0xffffffffu, s, o);
            if (f4 == 0)
                g_pb[chBase + 2 * i + half] = __float2bfloat16(s * (1.0f / 64.0f));
        }
    } else {
        const int NPER = DIM * DIM / 4;
        int i = (blockIdx.x - POOL_BLOCKS) * 256 + threadIdx.x;
        const float* src;
        bf16* dst;
        int j;
        if (i < NPER) { src = W1; dst = g_W1b; j = i; }
        else          { src = W2; dst = g_W2b; j = i - NPER; }
        float4 v = ((const float4*)src)[j];
        ((__nv_bfloat162*)dst)[j * 2]     = __floats2bfloat162_rn(v.x, v.y);
        ((__nv_bfloat162*)dst)[j * 2 + 1] = __floats2bfloat162_rn(v.z, v.w);
    }
}

// ---------------------------------------------------------------------------
// 2) bf16 GEMM: C[M,N] = A[M,K]*B[N,K]^T (+bias). 64x64 tile, 4 warps (2x2),
//    warp tile 32x32. 3-stage cp.async pipeline, ldmatrix.x4 fragments.
//    blockIdx.z = split-K chunk, writes into partial buffer z*Mtot*N.
// ---------------------------------------------------------------------------
#define BK 32
#define SPAD 40   // bf16 per smem row (80B): conflict-free ldmatrix

__global__ void __launch_bounds__(128, 4) gemm_kernel(
    const bf16* __restrict__ A, const bf16* __restrict__ Bm,
    float* __restrict__ C, const float* __restrict__ bias,
    int N, int K, int kChunk, int Mtot) {
    constexpr int BM = 64, BN = 64, TPB = 128;
    __shared__ bf16 As[3][BM * SPAD];
    __shared__ bf16 Bs[3][BN * SPAD];

    const int tid  = threadIdx.x;
    const int warp = tid >> 5;
    const int lane = tid & 31;
    const int wm = warp >> 1;
    const int wn = warp & 1;
    const int rowBase = blockIdx.y * BM;
    const int colBase = blockIdx.x * BN;
    const int kOff    = blockIdx.z * kChunk;
    float* Cout = C + (size_t)blockIdx.z * Mtot * N;

    const bf16* Ag = A + (size_t)rowBase * K + kOff;
    const bf16* Bg = Bm + (size_t)colBase * K + kOff;

    auto loadStage = [&](int st, int it) {
        int kb = it * BK;
#pragma unroll
        for (int c = tid; c < BM * 4; c += TPB) {
            int r = c >> 2, chk = c & 3;
            unsigned sa = smem_u32(&As[st][r * SPAD + chk * 8]);
            asm volatile("cp.async.cg.shared.global [%0], [%1], 16;\n"
                         :: "r"(sa), "l"(Ag + (size_t)r * K + kb + chk * 8));
        }
#pragma unroll
        for (int c = tid; c < BN * 4; c += TPB) {
            int r = c >> 2, chk = c & 3;
            unsigned sa = smem_u32(&Bs[st][r * SPAD + chk * 8]);
            asm volatile("cp.async.cg.shared.global [%0], [%1], 16;\n"
                         :: "r"(sa), "l"(Bg + (size_t)r * K + kb + chk * 8));
        }
        asm volatile("cp.async.commit_group;\n");
    };

    float acc[2][4][4];
#pragma unroll
    for (int i = 0; i < 2; i++)
#pragma unroll
        for (int j = 0; j < 4; j++)
#pragma unroll
            for (int k = 0; k < 4; k++) acc[i][j][k] = 0.f;

    const int NIT = kChunk / BK;
    loadStage(0, 0);
    loadStage(1, 1);

    const int arow = lane & 15;
    const int acol = (lane >> 4) * 8;

    for (int it = 0; it < NIT; ++it) {
        asm volatile("cp.async.wait_group 1;\n" ::: "memory");
        __syncthreads();
        if (it + 2 < NIT) loadStage((it + 2) % 3, it + 2);
        else asm volatile("cp.async.commit_group;\n");
        const int buf = it % 3;

#pragma unroll
        for (int ks = 0; ks < 2; ++ks) {
            unsigned afr[2][4], bfr[2][4];
#pragma unroll
            for (int mt = 0; mt < 2; mt++) {
                unsigned sa = smem_u32(
                    &As[buf][(wm * 32 + mt * 16 + arow) * SPAD + acol + ks * 16]);
                asm volatile(
                    "ldmatrix.sync.aligned.m8n8.x4.shared.b16 {%0,%1,%2,%3}, [%4];\n"
                    : "=r"(afr[mt][0]), "=r"(afr[mt][1]),
                      "=r"(afr[mt][2]), "=r"(afr[mt][3]) : "r"(sa));
            }
#pragma unroll
            for (int np = 0; np < 2; np++) {
                unsigned sa = smem_u32(
                    &Bs[buf][(wn * 32 + np * 16 + arow) * SPAD + acol + ks * 16]);
                asm volatile(
                    "ldmatrix.sync.aligned.m8n8.x4.shared.b16 {%0,%1,%2,%3}, [%4];\n"
                    : "=r"(bfr[np][0]), "=r"(bfr[np][1]),
                      "=r"(bfr[np][2]), "=r"(bfr[np][3]) : "r"(sa));
            }
#pragma unroll
            for (int mt = 0; mt < 2; mt++)
#pragma unroll
                for (int nt = 0; nt < 4; nt++) {
                    asm volatile(
                        "mma.sync.aligned.m16n8k16.row.col.f32.bf16.bf16.f32 "
                        "{%0,%1,%2,%3}, {%4,%5,%6,%7}, {%8,%9}, {%0,%1,%2,%3};\n"
                        : "+f"(acc[mt][nt][0]), "+f"(acc[mt][nt][1]),
                          "+f"(acc[mt][nt][2]), "+f"(acc[mt][nt][3])
                        : "r"(afr[mt][0]), "r"(afr[mt][1]),
                          "r"(afr[mt][2]), "r"(afr[mt][3]),
                          "r"(bfr[nt >> 1][nt & 1]), "r"(bfr[nt >> 1][2 + (nt & 1)]));
                }
        }
        __syncthreads();
    }

    const int g  = lane >> 2;
    const int t4 = lane & 3;
    const bool addb = (bias != nullptr) && (blockIdx.z == 0);
#pragma unroll
    for (int mt = 0; mt < 2; mt++) {
        int r0 = rowBase + wm * 32 + mt * 16 + g;
#pragma unroll
        for (int nt = 0; nt < 4; nt++) {
            int c0 = colBase + wn * 32 + nt * 8 + t4 * 2;
            float bx = addb ? bias[c0] : 0.f;
            float by = addb ? bias[c0 + 1] : 0.f;
            *(float2*)&Cout[(size_t)r0 * N + c0] =
                make_float2(acc[mt][nt][0] + bx, acc[mt][nt][1] + by);
            *(float2*)&Cout[(size_t)(r0 + 8) * N + c0] =
                make_float2(acc[mt][nt][2] + bx, acc[mt][nt][3] + by);
        }
    }
}

// ---------------------------------------------------------------------------
// 3) BN partial stats over combined h: grid (8, 32); 16 rows x 256 cols.
//    Partials stored TRANSPOSED: g_ps[col*32 + chunk] for coalesced finalize.
// ---------------------------------------------------------------------------
__global__ void bn_stats_kernel() {
    int col = blockIdx.x * 256 + threadIdx.x;
    int r0  = blockIdx.y * 16;
    float s = 0.f, q = 0.f;
#pragma unroll
    for (int r = 0; r < 16; r++) {
        size_t i = (size_t)(r0 + r) * DIM + col;
        float v = g_hp[i] + g_hp[TWOB * (size_t)DIM + i];
        s += v; q += v * v;
    }
    g_ps[col * 32 + blockIdx.y] = s;
    g_pq[col * 32 + blockIdx.y] = q;
}

// ---------------------------------------------------------------------------
// 4a) BN finalize: warp per column, lane per chunk — coalesced (256 blocks)
// ---------------------------------------------------------------------------
__global__ void bn_finalize_kernel(const float* __restrict__ gamma,
                                   const float* __restrict__ beta) {
    int col  = (blockIdx.x * 256 + threadIdx.x) >> 5;   // 0..DIM-1
    int lane = threadIdx.x & 31;
    float s = g_ps[col * 32 + lane];
    float q = g_pq[col * 32 + lane];
#pragma unroll
    for (int o = 16; o > 0; o >>= 1) {
        s += __shfl_xor_sync(0xffffffffu, s, o);
        q += __shfl_xor_sync(0xffffffffu, q, o);
    }
    if (lane == 0) {
        float mu   = s * (1.f / TWOB);
        float var  = q * (1.f / TWOB) - mu * mu;
        float istd = rsqrtf(var + BN_EPS);
        float ga = gamma[col] * istd;
        g_ga[col] = ga;
        g_be[col] = beta[col] - mu * ga;
    }
}

// ---------------------------------------------------------------------------
// 4b) BN apply + ReLU -> bf16: fully coalesced float4 walk (1024 blocks)
// ---------------------------------------------------------------------------
__global__ void bn_apply_kernel() {
    int i4 = blockIdx.x * 256 + threadIdx.x;      // float4 index
    int c4 = i4 & (DIM / 4 - 1);                  // float4 index within row
    float4 a = ((const float4*)g_hp)[i4];
    float4 b = ((const float4*)(g_hp + TWOB * (size_t)DIM))[i4];
    float4 ga = ((const float4*)g_ga)[c4];
    float4 be = ((const float4*)g_be)[c4];
    float v0 = fmaxf((a.x + b.x) * ga.x + be.x, 0.f);
    float v1 = fmaxf((a.y + b.y) * ga.y + be.y, 0.f);
    float v2 = fmaxf((a.z + b.z) * ga.z + be.z, 0.f);
    float v3 = fmaxf((a.w + b.w) * ga.w + be.w, 0.f);
    __nv_bfloat162* dst = (__nv_bfloat162*)g_hb;
    dst[i4 * 2]     = __floats2bfloat162_rn(v0, v1);
    dst[i4 * 2 + 1] = __floats2bfloat162_rn(v2, v3);
}

// ---------------------------------------------------------------------------
// 5) row L2 normalize (combines 2 z partials) -> bf16
// ---------------------------------------------------------------------------
__global__ void rownorm_kernel() {
    __shared__ float red[256];
    int r = blockIdx.x, tid = threadIdx.x;
    const float4* p0 = (const float4*)(g_zp + (size_t)r * DIM);
    const float4* p1 = (const float4*)(g_zp + TWOB * (size_t)DIM + (size_t)r * DIM);
    float4 a0 = p0[tid], a1 = p1[tid];
    float4 b0 = p0[tid + 256], b1 = p1[tid + 256];
    float4 a = make_float4(a0.x + a1.x, a0.y + a1.y, a0.z + a1.z, a0.w + a1.w);
    float4 b = make_float4(b0.x + b1.x, b0.y + b1.y, b0.z + b1.z, b0.w + b1.w);
    float s = a.x * a.x + a.y * a.y + a.z * a.z + a.w * a.w
            + b.x * b.x + b.y * b.y + b.z * b.z + b.w * b.w;
    red[tid] = s;
    __syncthreads();
    for (int o = 128; o > 0; o >>= 1) {
        if (tid < o) red[tid] += red[tid + o];
        __syncthreads();
    }
    float inv = 1.f / fmaxf(sqrtf(red[0]), COS_EPS);
    __nv_bfloat162* dst = (__nv_bfloat162*)(g_znb + (size_t)r * DIM);
    dst[tid * 2]             = __floats2bfloat162_rn(a.x * inv, a.y * inv);
    dst[tid * 2 + 1]         = __floats2bfloat162_rn(a.z * inv, a.w * inv);
    dst[(tid + 256) * 2]     = __floats2bfloat162_rn(b.x * inv, b.y * inv);
    dst[(tid + 256) * 2 + 1] = __floats2bfloat162_rn(b.z * inv, b.w * inv);
}

// ---------------------------------------------------------------------------
// 6) per-row contrastive loss (sums 4 K-partials) + fused final reduce
// ---------------------------------------------------------------------------
__global__ void loss_rows_kernel(const int* __restrict__ rel,
                                 float* __restrict__ out, int out_size) {
    __shared__ float red[256];
    __shared__ float rc[256];
    int i = blockIdx.x, j = threadIdx.x;
    int ri = rel[i];
    int rj = rel[j];
    float s1 = 0.f, s2 = 0.f;
#pragma unroll
    for (int p = 0; p < 4; p++) {
        s1 += g_simp[p * BATCH * TWOB + i * TWOB + j];
        s2 += g_simp[p * BATCH * TWOB + i * TWOB + BATCH + j];
    }
    float e1 = expf(s1 * INV_TEMP);
    float e2 = expf(s2 * INV_TEMP);
    int diff = ri - rj; if (diff < 0) diff = -diff;
    bool isneg = diff > SLICE_RANGE;
    bool ispos = (diff <= SLICE_RANGE) && (j != i);

    red[j] = (isneg ? e1 : 0.f) + e2;
    __syncthreads();
    for (int o = 128; o > 0; o >>= 1) {
        if (j < o) red[j] += red[j + o];
        __syncthreads();
    }
    float neg_sum = red[0];
    __syncthreads();

    red[j] = ispos ? (logf(e1 + neg_sum) - s1 * INV_TEMP) : 0.f;
    rc[j]  = ispos ? 1.f : 0.f;
    __syncthreads();
    for (int o = 128; o > 0; o >>= 1) {
        if (j < o) { red[j] += red[j + o]; rc[j] += rc[j + o]; }
        __syncthreads();
    }
    if (j == 0) {
        float cnt = rc[0];
        g_lossb[i] = (cnt > 0.f) ? (red[0] / cnt) : 0.f;
        g_cntd[i]  = (cnt > 0.f) ? 1.f : 0.f;
    }

    __threadfence();
    __shared__ unsigned ticket;
    if (j == 0) ticket = atomicAdd(&g_c2, 1u);
    __syncthreads();
    if (ticket == BATCH - 1) {
        if (j == 0) g_c2 = 0;   // reset for next graph replay
        __threadfence();
        red[j] = g_lossb[j];
        rc[j]  = g_cntd[j];
        __syncthreads();
        for (int o = 128; o > 0; o >>= 1) {
            if (j < o) { red[j] += red[j + o]; rc[j] += rc[j + o]; }
            __syncthreads();
        }
        if (j == 0) {
            out[0] = red[0];
            if (out_size > 1) out[1] = rc[0];
        }
    }
}

// ---------------------------------------------------------------------------
extern "C" void kernel_launch(void* const* d_in, const int* in_sizes, int n_in,
                              void* d_out, int out_size) {
    const float* z0    = (const float*)d_in[0];
    const float* z1    = (const float*)d_in[1];
    const int*   rel0  = (const int*)d_in[2];
    const float* W1    = (const float*)d_in[4];
    const float* b1    = (const float*)d_in[5];
    const float* gamma = (const float*)d_in[6];
    const float* beta  = (const float*)d_in[7];
    const float* W2    = (const float*)d_in[8];
    const float* b2    = (const float*)d_in[9];

    void *pb_, *w1b_, *w2b_, *hp_, *hb_, *zp_, *znb_, *simp_;
    cudaGetSymbolAddress(&pb_,  g_pb);
    cudaGetSymbolAddress(&w1b_, g_W1b);
    cudaGetSymbolAddress(&w2b_, g_W2b);
    cudaGetSymbolAddress(&hp_,  g_hp);
    cudaGetSymbolAddress(&hb_,  g_hb);
    cudaGetSymbolAddress(&zp_,  g_zp);
    cudaGetSymbolAddress(&znb_, g_znb);
    cudaGetSymbolAddress(&simp_, g_simp);

    // 1) pool (MLP=8) + weight conversion
    prep_kernel<<<POOL_BLOCKS + CVT_BLOCKS, 256>>>(z0, z1, W1, W2);
    // 2) GEMM1: h = p @ W1^T + b1, split-K=2 -> 512 CTAs
    gemm_kernel<<<dim3(DIM / 64, TWOB / 64, 2), 128>>>(
        (const bf16*)pb_, (const bf16*)w1b_, (float*)hp_, b1,
        DIM, DIM, DIM / 2, TWOB);
    // 3) BN stats over combined partials (transposed partial layout)
    bn_stats_kernel<<<dim3(8, 32), 256>>>();
    // 4) BN finalize (coalesced warp/column) then coalesced apply
    bn_finalize_kernel<<<DIM / 8, 256>>>(gamma, beta);
    bn_apply_kernel<<<(TWOB * DIM / 4) / 256, 256>>>();
    // 5) GEMM2: z = hb @ W2^T + b2, split-K=2 -> 512 CTAs
    gemm_kernel<<<dim3(DIM / 64, TWOB / 64, 2), 128>>>(
        (const bf16*)hb_, (const bf16*)w2b_, (float*)zp_, b2,
        DIM, DIM, DIM / 2, TWOB);
    // 6) row normalize (combine partials) -> bf16
    rownorm_kernel<<<TWOB, 256>>>();
    // 7) sim partials: 64x64 tiles, split-K=4 -> 128 CTAs
    gemm_kernel<<<dim3(TWOB / 64, BATCH / 64, 4), 128>>>(
        (const bf16*)znb_, (const bf16*)znb_, (float*)simp_, nullptr,
        TWOB, DIM, DIM / 4, BATCH);
    // 8) per-row loss + fused deterministic finalize
    loss_rows_kernel<<<BATCH, 256>>>(rel0, (float*)d_out, out_size);
}